// round 3
// baseline (speedup 1.0000x reference)
#include <cuda_runtime.h>

// ---------------- problem constants ----------------
#define BB 16          // batch
#define TT 20          // timesteps
#define HH 96
#define WW 96
#define CC 3           // in channels
#define FF 4           // filters
#define HP 95          // valid conv out
#define WP 95
#define PH 47          // pooled
#define PW 47
#define NPOS (HP*WP)   // 9025
#define NTHREADS 256
#define NBLK ((NPOS + NTHREADS - 1) / NTHREADS)   // 36

// ---------------- persistent device scratch (no allocs allowed) ----------------
__device__ float g_h[2][BB * NPOS * FF];   // ping-pong hidden state
__device__ float g_c[BB * NPOS * FF];      // cell state (updated in place)
__device__ float g_scratch[BB * NBLK];     // per-block partial dense sums

__device__ __forceinline__ float fsig(float x) {
    return __fdividef(1.f, 1.f + __expf(-x));
}
__device__ __forceinline__ float ftanh_fast(float x) {
    return 2.f * __fdividef(1.f, 1.f + __expf(-2.f * x)) - 1.f;
}

// One ConvLSTM timestep, fused with:
//   - input conv (VALID) computed on the fly
//   - maxpool+dense contribution of h_{t-1} (its 2x2 patch is already loaded)
// At t==0 the per-block dense partial is identically 0 and we OVERWRITE the
// scratch slot (resetting it for this graph replay); at t>0 we accumulate.
__global__ void __launch_bounds__(NTHREADS)
step_kernel(const float* __restrict__ x,
            const float* __restrict__ Kw,
            const float* __restrict__ RKw,
            const float* __restrict__ bias,
            const float* __restrict__ dw,
            int t)
{
    __shared__ float sK[2*2*CC*16];    // 192
    __shared__ float sRK[2*2*FF*16];   // 256
    __shared__ float sB[16];
    __shared__ float red[NTHREADS];

    const int tid = threadIdx.x;
    for (int i = tid; i < 192; i += NTHREADS) sK[i]  = Kw[i];
    for (int i = tid; i < 256; i += NTHREADS) sRK[i] = RKw[i];
    if (tid < 16) sB[tid] = bias[tid];
    __syncthreads();

    const int b = blockIdx.y;
    const int p = blockIdx.x * NTHREADS + tid;
    const bool active = (p < NPOS);
    const int i = p / WP;
    const int j = p % WP;

    const float* hprev = g_h[(t + 1) & 1] + (size_t)b * NPOS * FF;
    float*       hnew  = g_h[t & 1]       + (size_t)b * NPOS * FF;
    float*       cc    = g_c              + (size_t)b * NPOS * FF;

    float partial = 0.f;

    if (active) {
        float z[16];
        #pragma unroll
        for (int g = 0; g < 16; g++) z[g] = sB[g];

        // ---- input conv (VALID): rows i,i+1 / cols j,j+1 always in-bounds (<=95) ----
        const float* xb = x + ((((size_t)b * TT + t) * HH + i) * WW + j) * CC;
        #pragma unroll
        for (int di = 0; di < 2; di++)
        #pragma unroll
        for (int dj = 0; dj < 2; dj++) {
            const float* xp = xb + (di * WW + dj) * CC;
            #pragma unroll
            for (int ci = 0; ci < CC; ci++) {
                const float v = xp[ci];
                const float* kw = &sK[((di * 2 + dj) * CC + ci) * 16];
                #pragma unroll
                for (int g = 0; g < 16; g++) z[g] += v * kw[g];
            }
        }

        // ---- recurrent conv (SAME, pad_hi=1): h_prev[i+di, j+dj], zeros OOB ----
        float hv[4][4];
        if (t > 0) {
            #pragma unroll
            for (int di = 0; di < 2; di++)
            #pragma unroll
            for (int dj = 0; dj < 2; dj++) {
                const int q = di * 2 + dj;
                const int ii = i + di, jj = j + dj;
                float4 h4 = make_float4(0.f, 0.f, 0.f, 0.f);
                if (ii < HP && jj < WP)
                    h4 = *(const float4*)(hprev + ((size_t)(ii * WP + jj)) * 4);
                hv[q][0] = h4.x; hv[q][1] = h4.y; hv[q][2] = h4.z; hv[q][3] = h4.w;
                #pragma unroll
                for (int f = 0; f < 4; f++) {
                    const float v = hv[q][f];
                    const float* rw = &sRK[(q * 4 + f) * 16];
                    #pragma unroll
                    for (int g = 0; g < 16; g++) z[g] += v * rw[g];
                }
            }
        }

        // ---- gates (order i,f,g,o) + state update ----
        float4 cold = make_float4(0.f, 0.f, 0.f, 0.f);
        if (t > 0) cold = *(const float4*)(cc + (size_t)p * 4);
        const float cprev[4] = {cold.x, cold.y, cold.z, cold.w};
        float cn[4], hn[4];
        #pragma unroll
        for (int f = 0; f < 4; f++) {
            const float ig = fsig(z[f]);
            const float fg = fsig(z[4 + f]);
            const float gg = ftanh_fast(z[8 + f]);
            const float og = fsig(z[12 + f]);
            const float c2 = fg * cprev[f] + ig * gg;
            cn[f] = c2;
            hn[f] = og * ftanh_fast(c2);
        }
        *(float4*)(cc   + (size_t)p * 4) = make_float4(cn[0], cn[1], cn[2], cn[3]);
        *(float4*)(hnew + (size_t)p * 4) = make_float4(hn[0], hn[1], hn[2], hn[3]);

        // ---- maxpool(2x2) + dense contribution of h_{t-1} (patch already loaded) ----
        if (t > 0 && ((i & 1) == 0) && ((j & 1) == 0) && i < 94 && j < 94) {
            const int ph = i >> 1, pw = j >> 1;
            const float* w4 = dw + ((((size_t)(t - 1) * PH + ph) * PW + pw) * 4);
            #pragma unroll
            for (int f = 0; f < 4; f++) {
                const float m = fmaxf(fmaxf(hv[0][f], hv[1][f]),
                                      fmaxf(hv[2][f], hv[3][f]));
                partial += m * w4[f];
            }
        }
    }

    // ---- deterministic block reduction into fixed scratch slot ----
    red[tid] = partial;
    __syncthreads();
    #pragma unroll
    for (int s = NTHREADS / 2; s > 0; s >>= 1) {
        if (tid < s) red[tid] += red[tid + s];
        __syncthreads();
    }
    if (tid == 0) {
        const int slot = b * NBLK + blockIdx.x;
        g_scratch[slot] = (t == 0) ? red[0] : (g_scratch[slot] + red[0]);
    }
}

// Final step: pool+dense for h_{T-1}, sum scratch, add dense bias.
__global__ void __launch_bounds__(256)
epilogue_kernel(const float* __restrict__ dw,
                const float* __restrict__ db,
                float* __restrict__ out)
{
    __shared__ float red[256];
    const int b = blockIdx.x;
    const int tid = threadIdx.x;
    const float* hlast = g_h[(TT - 1) & 1] + (size_t)b * NPOS * FF;

    float partial = 0.f;
    for (int pos = tid; pos < PH * PW; pos += 256) {
        const int ph = pos / PW, pw = pos % PW;
        const int i = ph * 2, j = pw * 2;
        float m0 = -1e30f, m1 = -1e30f, m2 = -1e30f, m3 = -1e30f;
        #pragma unroll
        for (int di = 0; di < 2; di++)
        #pragma unroll
        for (int dj = 0; dj < 2; dj++) {
            const float4 h4 = *(const float4*)(hlast + ((size_t)((i + di) * WP + (j + dj))) * 4);
            m0 = fmaxf(m0, h4.x); m1 = fmaxf(m1, h4.y);
            m2 = fmaxf(m2, h4.z); m3 = fmaxf(m3, h4.w);
        }
        const float* w4 = dw + ((((size_t)(TT - 1) * PH + ph) * PW + pw) * 4);
        partial += m0 * w4[0] + m1 * w4[1] + m2 * w4[2] + m3 * w4[3];
    }
    red[tid] = partial;
    __syncthreads();
    #pragma unroll
    for (int s = 128; s > 0; s >>= 1) {
        if (tid < s) red[tid] += red[tid + s];
        __syncthreads();
    }
    if (tid == 0) {
        float acc = red[0];
        for (int k = 0; k < NBLK; k++) acc += g_scratch[b * NBLK + k];
        out[b] = acc + db[0];
    }
}

extern "C" void kernel_launch(void* const* d_in, const int* in_sizes, int n_in,
                              void* d_out, int out_size) {
    const float* x    = (const float*)d_in[0];
    const float* Kw   = (const float*)d_in[1];
    const float* RKw  = (const float*)d_in[2];
    const float* bias = (const float*)d_in[3];
    const float* dw   = (const float*)d_in[4];
    const float* db   = (const float*)d_in[5];
    float* out = (float*)d_out;

    dim3 grid(NBLK, BB);
    for (int t = 0; t < TT; t++)
        step_kernel<<<grid, NTHREADS>>>(x, Kw, RKw, bias, dw, t);
    epilogue_kernel<<<BB, 256>>>(dw, db, out);
}

// round 4
// speedup vs baseline: 1.0756x; 1.0756x over previous
#include <cuda_runtime.h>

// ---------------- problem constants ----------------
#define BB 16          // batch
#define TT 20          // timesteps
#define HH 96
#define WW 96
#define CC 3           // in channels
#define FF 4           // filters
#define HP 95          // valid conv out
#define WP 95
#define PH 47          // pooled
#define PW 47
#define NPOS (HP*WP)   // 9025
#define NTHREADS 256
#define NBLK ((NPOS + NTHREADS - 1) / NTHREADS)   // 36

// ---------------- persistent device scratch (no allocs allowed) ----------------
__device__ float g_h[2][BB * NPOS * FF];   // ping-pong hidden state
__device__ float g_c[BB * NPOS * FF];      // cell state (updated in place)
__device__ float g_scratch[BB * NBLK];     // per-block partial dense sums

__device__ __forceinline__ float ftanh(float x) {
    float y;
    asm("tanh.approx.f32 %0, %1;" : "=f"(y) : "f"(x));
    return y;
}
__device__ __forceinline__ float fsig(float x) {
    return fmaf(ftanh(0.5f * x), 0.5f, 0.5f);
}

// One ConvLSTM timestep, fused with:
//   - input conv (VALID) computed on the fly
//   - maxpool+dense contribution of h_{t-1} (its 2x2 patch is already loaded)
// At t==0 the per-block dense partial is identically 0 and we OVERWRITE the
// scratch slot (resetting it for this graph replay); at t>0 we accumulate.
__global__ void __launch_bounds__(NTHREADS)
step_kernel(const float* __restrict__ x,
            const float4* __restrict__ Kw,    // 48 float4  (2*2*3*16 floats)
            const float4* __restrict__ RKw,   // 64 float4  (2*2*4*16 floats)
            const float4* __restrict__ bias,  // 4 float4
            const float* __restrict__ dw,
            int t)
{
    __shared__ float4 sK[48];     // [q*3+ci][g4]  gates-contiguous
    __shared__ float4 sRK[64];    // [q*4+f][g4]
    __shared__ float4 sB[4];
    __shared__ float warpsum[NTHREADS / 32];

    const int tid = threadIdx.x;
    if (tid < 48) sK[tid]  = Kw[tid];
    if (tid < 64) sRK[tid] = RKw[tid];
    if (tid < 4)  sB[tid]  = bias[tid];
    __syncthreads();

    const int b = blockIdx.y;
    const int p = blockIdx.x * NTHREADS + tid;
    const bool active = (p < NPOS);
    const int i = p / WP;
    const int j = p % WP;

    const float* hprev = g_h[(t + 1) & 1] + (size_t)b * NPOS * FF;
    float*       hnew  = g_h[t & 1]       + (size_t)b * NPOS * FF;
    float*       cc    = g_c              + (size_t)b * NPOS * FF;

    float partial = 0.f;

    if (active) {
        float4 z[4];   // 16 gate pre-activations, 4 gates per float4
        #pragma unroll
        for (int g4 = 0; g4 < 4; g4++) z[g4] = sB[g4];

        // ---- input conv (VALID): rows i,i+1 / cols j,j+1 always in-bounds ----
        const float* xb = x + ((((size_t)b * TT + t) * HH + i) * WW + j) * CC;
        #pragma unroll
        for (int q = 0; q < 4; q++) {
            const int di = q >> 1, dj = q & 1;
            const float* xp = xb + (di * WW + dj) * CC;
            #pragma unroll
            for (int ci = 0; ci < CC; ci++) {
                const float v = xp[ci];
                const float4* kw = &sK[(q * 3 + ci) * 4];
                #pragma unroll
                for (int g4 = 0; g4 < 4; g4++) {
                    const float4 w = kw[g4];
                    z[g4].x += v * w.x; z[g4].y += v * w.y;
                    z[g4].z += v * w.z; z[g4].w += v * w.w;
                }
            }
        }

        // ---- recurrent conv (SAME, pad_hi=1): h_prev[i+di, j+dj], zeros OOB ----
        float hv[4][4];
        if (t > 0) {
            #pragma unroll
            for (int q = 0; q < 4; q++) {
                const int di = q >> 1, dj = q & 1;
                const int ii = i + di, jj = j + dj;
                float4 h4 = make_float4(0.f, 0.f, 0.f, 0.f);
                if (ii < HP && jj < WP)
                    h4 = *(const float4*)(hprev + ((size_t)(ii * WP + jj)) * 4);
                hv[q][0] = h4.x; hv[q][1] = h4.y; hv[q][2] = h4.z; hv[q][3] = h4.w;
                #pragma unroll
                for (int f = 0; f < 4; f++) {
                    const float v = hv[q][f];
                    const float4* rw = &sRK[(q * 4 + f) * 4];
                    #pragma unroll
                    for (int g4 = 0; g4 < 4; g4++) {
                        const float4 w = rw[g4];
                        z[g4].x += v * w.x; z[g4].y += v * w.y;
                        z[g4].z += v * w.z; z[g4].w += v * w.w;
                    }
                }
            }
        }

        // ---- gates (order i,f,g,o) + state update ----
        float4 cold = make_float4(0.f, 0.f, 0.f, 0.f);
        if (t > 0) cold = *(const float4*)(cc + (size_t)p * 4);
        const float zi[4] = {z[0].x, z[0].y, z[0].z, z[0].w};
        const float zf[4] = {z[1].x, z[1].y, z[1].z, z[1].w};
        const float zg[4] = {z[2].x, z[2].y, z[2].z, z[2].w};
        const float zo[4] = {z[3].x, z[3].y, z[3].z, z[3].w};
        const float cprev[4] = {cold.x, cold.y, cold.z, cold.w};
        float cn[4], hn[4];
        #pragma unroll
        for (int f = 0; f < 4; f++) {
            const float ig = fsig(zi[f]);
            const float fg = fsig(zf[f]);
            const float gg = ftanh(zg[f]);
            const float og = fsig(zo[f]);
            const float c2 = fg * cprev[f] + ig * gg;
            cn[f] = c2;
            hn[f] = og * ftanh(c2);
        }
        *(float4*)(cc   + (size_t)p * 4) = make_float4(cn[0], cn[1], cn[2], cn[3]);
        *(float4*)(hnew + (size_t)p * 4) = make_float4(hn[0], hn[1], hn[2], hn[3]);

        // ---- maxpool(2x2) + dense contribution of h_{t-1} (patch already loaded) ----
        if (t > 0 && ((i & 1) == 0) && ((j & 1) == 0) && i < 94 && j < 94) {
            const int ph = i >> 1, pw = j >> 1;
            // dw row for this pooled position: 4 floats, 16B-aligned by construction
            const float4 w4 = *(const float4*)(dw + ((((size_t)(t - 1) * PH + ph) * PW + pw) * 4));
            const float m0 = fmaxf(fmaxf(hv[0][0], hv[1][0]), fmaxf(hv[2][0], hv[3][0]));
            const float m1 = fmaxf(fmaxf(hv[0][1], hv[1][1]), fmaxf(hv[2][1], hv[3][1]));
            const float m2 = fmaxf(fmaxf(hv[0][2], hv[1][2]), fmaxf(hv[2][2], hv[3][2]));
            const float m3 = fmaxf(fmaxf(hv[0][3], hv[1][3]), fmaxf(hv[2][3], hv[3][3]));
            partial = m0 * w4.x + m1 * w4.y + m2 * w4.z + m3 * w4.w;
        }
    }

    // ---- deterministic reduction: warp shuffle, then thread 0 sums 8 warps ----
    #pragma unroll
    for (int off = 16; off > 0; off >>= 1)
        partial += __shfl_down_sync(0xFFFFFFFFu, partial, off);
    if ((tid & 31) == 0) warpsum[tid >> 5] = partial;
    __syncthreads();
    if (tid == 0) {
        float s = 0.f;
        #pragma unroll
        for (int w = 0; w < NTHREADS / 32; w++) s += warpsum[w];
        const int slot = b * NBLK + blockIdx.x;
        g_scratch[slot] = (t == 0) ? s : (g_scratch[slot] + s);
    }
}

// Final step: pool+dense for h_{T-1}, sum scratch, add dense bias.
__global__ void __launch_bounds__(256)
epilogue_kernel(const float* __restrict__ dw,
                const float* __restrict__ db,
                float* __restrict__ out)
{
    __shared__ float warpsum[8];
    const int b = blockIdx.x;
    const int tid = threadIdx.x;
    const float* hlast = g_h[(TT - 1) & 1] + (size_t)b * NPOS * FF;

    float partial = 0.f;
    for (int pos = tid; pos < PH * PW; pos += 256) {
        const int ph = pos / PW, pw = pos % PW;
        const int i = ph * 2, j = pw * 2;
        float m0 = -1e30f, m1 = -1e30f, m2 = -1e30f, m3 = -1e30f;
        #pragma unroll
        for (int di = 0; di < 2; di++)
        #pragma unroll
        for (int dj = 0; dj < 2; dj++) {
            const float4 h4 = *(const float4*)(hlast + ((size_t)((i + di) * WP + (j + dj))) * 4);
            m0 = fmaxf(m0, h4.x); m1 = fmaxf(m1, h4.y);
            m2 = fmaxf(m2, h4.z); m3 = fmaxf(m3, h4.w);
        }
        const float4 w4 = *(const float4*)(dw + ((((size_t)(TT - 1) * PH + ph) * PW + pw) * 4));
        partial += m0 * w4.x + m1 * w4.y + m2 * w4.z + m3 * w4.w;
    }
    #pragma unroll
    for (int off = 16; off > 0; off >>= 1)
        partial += __shfl_down_sync(0xFFFFFFFFu, partial, off);
    if ((tid & 31) == 0) warpsum[tid >> 5] = partial;
    __syncthreads();
    if (tid == 0) {
        float acc = 0.f;
        #pragma unroll
        for (int w = 0; w < 8; w++) acc += warpsum[w];
        for (int k = 0; k < NBLK; k++) acc += g_scratch[b * NBLK + k];
        out[b] = acc + db[0];
    }
}

extern "C" void kernel_launch(void* const* d_in, const int* in_sizes, int n_in,
                              void* d_out, int out_size) {
    const float*  x    = (const float*)d_in[0];
    const float4* Kw   = (const float4*)d_in[1];
    const float4* RKw  = (const float4*)d_in[2];
    const float4* bias = (const float4*)d_in[3];
    const float*  dw   = (const float*)d_in[4];
    const float*  db   = (const float*)d_in[5];
    float* out = (float*)d_out;

    dim3 grid(NBLK, BB);
    for (int t = 0; t < TT; t++)
        step_kernel<<<grid, NTHREADS>>>(x, Kw, RKw, bias, dw, t);
    epilogue_kernel<<<BB, 256>>>(dw, db, out);
}